// round 3
// baseline (speedup 1.0000x reference)
#include <cuda_runtime.h>

// Problem constants (fixed shapes)
#define E_EDGES   320000
#define N_ATOMS_C 20000
#define TRIP_CAP_C 4000000
#define SCAN_TILE 4096
#define NB_CNT ((E_EDGES + SCAN_TILE - 1) / SCAN_TILE)   // 79

// ---------------- scratch (device globals; no allocation allowed) ----------
__device__ int g_row[E_EDGES];     // source node if edge valid, else -1
__device__ int g_deg[N_ATOMS_C];   // valid degree per node
__device__ int g_start[N_ATOMS_C]; // bucket start offset per node
__device__ int g_cur[N_ATOMS_C];   // scatter cursor per node
__device__ int g_bucket[E_EDGES];  // valid edge ids, grouped per node, sorted asc
__device__ int g_off[E_EDGES];     // per-edge output offset (within-tile exclusive)
__device__ int g_bsum[NB_CNT];     // per-tile sums -> exclusive tile offsets

// ---------------- block-wide exclusive scan helper -------------------------
__device__ __forceinline__ int block_exscan(int v) {
    __shared__ int ws[32];
    int lane = threadIdx.x & 31, wid = threadIdx.x >> 5;
    int nw = (blockDim.x + 31) >> 5;
    int x = v;
#pragma unroll
    for (int o = 1; o < 32; o <<= 1) {
        int y = __shfl_up_sync(0xffffffffu, x, o);
        if (lane >= o) x += y;
    }
    if (lane == 31) ws[wid] = x;      // warp inclusive total
    __syncthreads();
    if (wid == 0) {
        int wv = (lane < nw) ? ws[lane] : 0;
        int wx = wv;
#pragma unroll
        for (int o = 1; o < 32; o <<= 1) {
            int y = __shfl_up_sync(0xffffffffu, wx, o);
            if (lane >= o) wx += y;
        }
        ws[lane] = wx - wv;           // exclusive warp offsets
    }
    __syncthreads();
    return ws[wid] + x - v;           // block-exclusive prefix of v
}

// ---------------- kernels ---------------------------------------------------

// Fill whole output with -1.0f (output dtype is float32).
__global__ void k_fill(float* __restrict__ out, int n) {
    int n4 = n >> 2;
    float4 v = make_float4(-1.0f, -1.0f, -1.0f, -1.0f);
    float4* o4 = (float4*)out;
    for (int i = blockIdx.x * blockDim.x + threadIdx.x; i < n4;
         i += gridDim.x * blockDim.x)
        o4[i] = v;
    int t = (n4 << 2) + blockIdx.x * blockDim.x + threadIdx.x;
    if (t < n) out[t] = -1.0f;
}

__global__ void k_zero_deg() {
    int i = blockIdx.x * blockDim.x + threadIdx.x;
    if (i < N_ATOMS_C) g_deg[i] = 0;
}

// Validity + degree histogram. edge_index delivered as int32;
// row = first E elements of the [2, E] tensor.
__global__ void k_classify(const float* __restrict__ vec,
                           const int* __restrict__ ei_row) {
    int e = blockIdx.x * blockDim.x + threadIdx.x;
    if (e >= E_EDGES) return;
    float x = vec[3 * e + 0], y = vec[3 * e + 1], z = vec[3 * e + 2];
    float s = __fadd_rn(__fadd_rn(__fmul_rn(x, x), __fmul_rn(y, y)),
                        __fmul_rn(z, z));
    float nrm = sqrtf(s);
    if (nrm <= 1.5f) {
        int r = ei_row[e];
        if (r >= 0 && r < N_ATOMS_C) {
            g_row[e] = r;
            atomicAdd(&g_deg[r], 1);
        } else {
            g_row[e] = -1;
        }
    } else {
        g_row[e] = -1;
    }
}

// Exclusive scan of node degrees (single block, 1024 threads, 20 items each).
__global__ void k_scan_nodes() {
    const int PER = 20;               // 1024*20 = 20480 >= 20000
    int t = threadIdx.x;
    int base = t * PER;
    int vals[PER];
    int local = 0;
#pragma unroll
    for (int i = 0; i < PER; i++) {
        int idx = base + i;
        vals[i] = (idx < N_ATOMS_C) ? g_deg[idx] : 0;
        local += vals[i];
    }
    int ex = block_exscan(local);
    int run = ex;
#pragma unroll
    for (int i = 0; i < PER; i++) {
        int idx = base + i;
        if (idx < N_ATOMS_C) { g_start[idx] = run; g_cur[idx] = run; }
        run += vals[i];
    }
}

// Scatter valid edge ids into per-node buckets (unordered).
__global__ void k_scatter() {
    int e = blockIdx.x * blockDim.x + threadIdx.x;
    if (e >= E_EDGES) return;
    int r = g_row[e];
    if (r < 0) return;
    int p = atomicAdd(&g_cur[r], 1);
    if (p >= 0 && p < E_EDGES) g_bucket[p] = e;
}

// Sort each node's bucket ascending (tiny insertion sort, deg ~ 8).
__global__ void k_sort() {
    int n = blockIdx.x * blockDim.x + threadIdx.x;
    if (n >= N_ATOMS_C) return;
    int s = g_start[n], d = g_deg[n];
    for (int i = 1; i < d; i++) {
        int key = g_bucket[s + i];
        int j = i - 1;
        while (j >= 0 && g_bucket[s + j] > key) {
            g_bucket[s + j + 1] = g_bucket[s + j];
            j--;
        }
        g_bucket[s + j + 1] = key;
    }
}

// Per-tile exclusive scan of per-edge triplet counts (deg[row]-1 if valid).
__global__ void k_scan_cnt() {
    int base = blockIdx.x * SCAN_TILE + threadIdx.x * 4;
    int c[4];
    int s = 0;
#pragma unroll
    for (int i = 0; i < 4; i++) {
        int e = base + i;
        int cc = 0;
        if (e < E_EDGES) {
            int r = g_row[e];
            if (r >= 0) cc = g_deg[r] - 1;
        }
        c[i] = cc;
        s += cc;
    }
    int pre = block_exscan(s);
    int run = pre;
#pragma unroll
    for (int i = 0; i < 4; i++) {
        int e = base + i;
        if (e < E_EDGES) g_off[e] = run;
        run += c[i];
    }
    if (threadIdx.x == blockDim.x - 1) g_bsum[blockIdx.x] = pre + s;
}

// Exclusive scan of the 79 tile sums (single small block).
__global__ void k_scan_small() {
    int t = threadIdx.x;
    int v = (t < NB_CNT) ? g_bsum[t] : 0;
    int ex = block_exscan(v);
    if (t < NB_CNT) g_bsum[t] = ex;
}

// Emit triplets as float32. off monotone in e => adjacent threads write
// adjacent runs (coalesced-ish).
__global__ void k_emit(float* __restrict__ out) {
    int e = blockIdx.x * blockDim.x + threadIdx.x;
    if (e >= E_EDGES) return;
    int r = g_row[e];
    if (r < 0) return;
    int d = g_deg[r];
    int s = g_start[r];
    int o = g_off[e] + g_bsum[e / SCAN_TILE];
    float* oj = out;                 // idx_ij
    float* ok = out + TRIP_CAP_C;    // idx_kj
    float fe = (float)e;             // < 2^24, exact
    int w = 0;
    for (int i = 0; i < d; i++) {
        int k = g_bucket[s + i];
        if (k != e) {
            int p = o + w;
            if (p >= 0 && p < TRIP_CAP_C) {  // OOB guard
                oj[p] = fe;
                ok[p] = (float)k;
            }
            w++;
        }
    }
}

// ---------------- launch -----------------------------------------------------
extern "C" void kernel_launch(void* const* d_in, const int* in_sizes, int n_in,
                              void* d_out, int out_size) {
    const float* vec    = (const float*)d_in[0];
    const int*   ei_row = (const int*)d_in[1];   // [2, E] int32; row = first E
    float* out = (float*)d_out;

    k_fill<<<2048, 256>>>(out, out_size);
    k_zero_deg<<<(N_ATOMS_C + 255) / 256, 256>>>();
    k_classify<<<(E_EDGES + 255) / 256, 256>>>(vec, ei_row);
    k_scan_nodes<<<1, 1024>>>();
    k_scatter<<<(E_EDGES + 255) / 256, 256>>>();
    k_sort<<<(N_ATOMS_C + 255) / 256, 256>>>();
    k_scan_cnt<<<NB_CNT, 1024>>>();
    k_scan_small<<<1, 128>>>();
    k_emit<<<(E_EDGES + 255) / 256, 256>>>(out);
}

// round 4
// speedup vs baseline: 1.6651x; 1.6651x over previous
#include <cuda_runtime.h>

// Problem constants (fixed shapes)
#define E_EDGES   320000
#define N_ATOMS_C 20000
#define TRIP_CAP_C 4000000
#define SCAN_TILE 4096
#define NB_CNT ((E_EDGES + SCAN_TILE - 1) / SCAN_TILE)   // 79

// ---------------- scratch (device globals; no allocation allowed) ----------
__device__ int g_row[E_EDGES];     // source node if edge valid, else -1
__device__ int g_deg[N_ATOMS_C];   // valid degree per node
__device__ int g_start[N_ATOMS_C]; // bucket start offset per node
__device__ int g_cur[N_ATOMS_C];   // scatter cursor per node
__device__ int g_bucket[E_EDGES];  // valid edge ids, per-node contiguous, sorted
__device__ int g_off[E_EDGES];     // per-edge output offset (within-tile exclusive)
__device__ int g_bsum[NB_CNT];     // per-tile sums -> exclusive tile offsets
__device__ int g_total;            // bucket allocator cursor
__device__ int g_ntrip;            // total triplet count (for tail fill)

// ---------------- block-wide exclusive scan helper -------------------------
__device__ __forceinline__ int block_exscan(int v) {
    __shared__ int ws[32];
    int lane = threadIdx.x & 31, wid = threadIdx.x >> 5;
    int nw = (blockDim.x + 31) >> 5;
    int x = v;
#pragma unroll
    for (int o = 1; o < 32; o <<= 1) {
        int y = __shfl_up_sync(0xffffffffu, x, o);
        if (lane >= o) x += y;
    }
    if (lane == 31) ws[wid] = x;      // warp inclusive total
    __syncthreads();
    if (wid == 0) {
        int wv = (lane < nw) ? ws[lane] : 0;
        int wx = wv;
#pragma unroll
        for (int o = 1; o < 32; o <<= 1) {
            int y = __shfl_up_sync(0xffffffffu, wx, o);
            if (lane >= o) wx += y;
        }
        ws[lane] = wx - wv;           // exclusive warp offsets
    }
    __syncthreads();
    return ws[wid] + x - v;           // block-exclusive prefix of v
}

// ---------------- kernels ---------------------------------------------------

// Zero per-node degree + allocator cursors (must reset every call: graph replay).
__global__ void k_init() {
    int i = blockIdx.x * blockDim.x + threadIdx.x;
    if (i < N_ATOMS_C) g_deg[i] = 0;
    if (i == 0) { g_total = 0; g_ntrip = 0; }
}

// Validity + degree histogram. edge_index delivered as int32;
// row = first E elements of the [2, E] tensor.
__global__ void k_classify(const float* __restrict__ vec,
                           const int* __restrict__ ei_row) {
    int e = blockIdx.x * blockDim.x + threadIdx.x;
    if (e >= E_EDGES) return;
    float x = vec[3 * e + 0], y = vec[3 * e + 1], z = vec[3 * e + 2];
    float s = __fadd_rn(__fadd_rn(__fmul_rn(x, x), __fmul_rn(y, y)),
                        __fmul_rn(z, z));
    float nrm = sqrtf(s);
    int r = -1;
    if (nrm <= 1.5f) {
        int rr = ei_row[e];
        if (rr >= 0 && rr < N_ATOMS_C) {
            r = rr;
            atomicAdd(&g_deg[rr], 1);
        }
    }
    g_row[e] = r;
}

// Per-node bucket allocation via atomic bump allocator.
// Placement inside g_bucket is irrelevant to output — only per-node
// contiguity + sortedness matter. Fully parallel, replaces the serial scan.
__global__ void k_alloc() {
    int n = blockIdx.x * blockDim.x + threadIdx.x;
    if (n >= N_ATOMS_C) return;
    int d = g_deg[n];
    int s = (d > 0) ? atomicAdd(&g_total, d) : 0;
    g_start[n] = s;
    g_cur[n]   = s;
}

// Scatter valid edge ids into per-node buckets (unordered).
__global__ void k_scatter() {
    int e = blockIdx.x * blockDim.x + threadIdx.x;
    if (e >= E_EDGES) return;
    int r = g_row[e];
    if (r < 0) return;
    int p = atomicAdd(&g_cur[r], 1);
    if (p >= 0 && p < E_EDGES) g_bucket[p] = e;
}

// Sort each node's bucket ascending (tiny insertion sort, deg ~ 8).
__global__ void k_sort() {
    int n = blockIdx.x * blockDim.x + threadIdx.x;
    if (n >= N_ATOMS_C) return;
    int s = g_start[n], d = g_deg[n];
    for (int i = 1; i < d; i++) {
        int key = g_bucket[s + i];
        int j = i - 1;
        while (j >= 0 && g_bucket[s + j] > key) {
            g_bucket[s + j + 1] = g_bucket[s + j];
            j--;
        }
        g_bucket[s + j + 1] = key;
    }
}

// Per-tile exclusive scan of per-edge triplet counts (deg[row]-1 if valid).
__global__ void k_scan_cnt() {
    int base = blockIdx.x * SCAN_TILE + threadIdx.x * 4;
    int c[4];
    int s = 0;
#pragma unroll
    for (int i = 0; i < 4; i++) {
        int e = base + i;
        int cc = 0;
        if (e < E_EDGES) {
            int r = g_row[e];
            if (r >= 0) cc = g_deg[r] - 1;
        }
        c[i] = cc;
        s += cc;
    }
    int pre = block_exscan(s);
    int run = pre;
#pragma unroll
    for (int i = 0; i < 4; i++) {
        int e = base + i;
        if (e < E_EDGES) g_off[e] = run;
        run += c[i];
    }
    if (threadIdx.x == blockDim.x - 1) g_bsum[blockIdx.x] = pre + s;
}

// Exclusive scan of the 79 tile sums; also records the grand total.
__global__ void k_scan_small() {
    int t = threadIdx.x;
    int v = (t < NB_CNT) ? g_bsum[t] : 0;
    int ex = block_exscan(v);
    if (t < NB_CNT) g_bsum[t] = ex;
    if (t == NB_CNT - 1) g_ntrip = ex + v;
}

// Fill only the dead tail [count, TRIP_CAP) of both halves with -1.0f.
// Emit overwrites [0, count), so this is the only region needing the pad.
__global__ void k_fill_tail(float* __restrict__ out) {
    int cnt = g_ntrip;
    if (cnt < 0) cnt = 0;
    if (cnt > TRIP_CAP_C) cnt = TRIP_CAP_C;
    int start4 = (cnt + 3) & ~3;           // round UP: never touch live region
    int tid = blockIdx.x * blockDim.x + threadIdx.x;
    // head scalars (0-3 per half)
    int head = start4 - cnt;
    if (start4 > TRIP_CAP_C) { start4 = TRIP_CAP_C; head = TRIP_CAP_C - cnt; }
    if (tid < head) {
        out[cnt + tid] = -1.0f;
        out[TRIP_CAP_C + cnt + tid] = -1.0f;
    }
    int n4 = (TRIP_CAP_C - start4) >> 2;   // TRIP_CAP_C % 4 == 0
    float4 v = make_float4(-1.0f, -1.0f, -1.0f, -1.0f);
    float4* a = (float4*)(out + start4);
    float4* b = (float4*)(out + TRIP_CAP_C + start4);
    for (int i = tid; i < n4; i += gridDim.x * blockDim.x) {
        a[i] = v;
        b[i] = v;
    }
}

// Emit triplets as float32. off monotone in e => adjacent threads write
// adjacent runs (coalesced-ish).
__global__ void k_emit(float* __restrict__ out) {
    int e = blockIdx.x * blockDim.x + threadIdx.x;
    if (e >= E_EDGES) return;
    int r = g_row[e];
    if (r < 0) return;
    int d = g_deg[r];
    int s = g_start[r];
    int o = g_off[e] + g_bsum[e / SCAN_TILE];
    float* oj = out;                 // idx_ij
    float* ok = out + TRIP_CAP_C;    // idx_kj
    float fe = (float)e;             // < 2^24, exact
    int w = 0;
    for (int i = 0; i < d; i++) {
        int k = g_bucket[s + i];
        if (k != e) {
            int p = o + w;
            if (p >= 0 && p < TRIP_CAP_C) {  // OOB guard
                oj[p] = fe;
                ok[p] = (float)k;
            }
            w++;
        }
    }
}

// ---------------- launch -----------------------------------------------------
extern "C" void kernel_launch(void* const* d_in, const int* in_sizes, int n_in,
                              void* d_out, int out_size) {
    const float* vec    = (const float*)d_in[0];
    const int*   ei_row = (const int*)d_in[1];   // [2, E] int32; row = first E
    float* out = (float*)d_out;

    k_init<<<(N_ATOMS_C + 255) / 256, 256>>>();
    k_classify<<<(E_EDGES + 255) / 256, 256>>>(vec, ei_row);
    k_alloc<<<(N_ATOMS_C + 255) / 256, 256>>>();
    k_scatter<<<(E_EDGES + 255) / 256, 256>>>();
    k_sort<<<(N_ATOMS_C + 255) / 256, 256>>>();
    k_scan_cnt<<<NB_CNT, 1024>>>();
    k_scan_small<<<1, 128>>>();
    k_fill_tail<<<2048, 256>>>(out);
    k_emit<<<(E_EDGES + 255) / 256, 256>>>(out);
}